// round 10
// baseline (speedup 1.0000x reference)
#include <cuda_runtime.h>
#include <math.h>
#include <stdint.h>

// Problem constants
constexpr int B_   = 8;
constexpr int N_   = 1025;
constexpr int H_   = 12;
constexpr int HD_  = 64;
constexpr int DIM_ = 768;
constexpr int NTOK = B_ * N_;     // 8200
constexpr int C3   = 3 * DIM_;    // 2304
constexpr int BH   = B_ * H_;     // 96
constexpr float SCALE = 0.125f;

// Scratch (tf32-rounded-in-fp32 unless noted)
__device__ float g_Q[(size_t)BH * N_ * HD_];
__device__ float g_K[(size_t)BH * N_ * HD_];
__device__ float g_V[(size_t)BH * N_ * HD_];
__device__ float g_col0[BH * N_];              // fp32
__device__ float g_row0[BH * N_];              // fp32
__device__ float g_att[(size_t)NTOK * DIM_];
__device__ float g_xt[(size_t)NTOK * DIM_];
__device__ float g_wqkvt[C3 * DIM_];
__device__ float g_wprojt[DIM_ * DIM_];

// ---------------------------------------------------------------------------
__device__ __forceinline__ uint32_t f2tf(float f) {
    uint32_t u;
    asm("cvt.rna.tf32.f32 %0, %1;" : "=r"(u) : "f"(f));
    return u;
}

__device__ __forceinline__ void mma_tf32(float* d, const uint32_t* a, const uint32_t* b) {
    asm volatile(
        "mma.sync.aligned.m16n8k8.row.col.f32.tf32.tf32.f32 "
        "{%0,%1,%2,%3}, {%4,%5,%6,%7}, {%8,%9}, {%0,%1,%2,%3};\n"
        : "+f"(d[0]), "+f"(d[1]), "+f"(d[2]), "+f"(d[3])
        : "r"(a[0]), "r"(a[1]), "r"(a[2]), "r"(a[3]), "r"(b[0]), "r"(b[1]));
}

__device__ __forceinline__ void bar_named(int id, int cnt) {
    asm volatile("bar.sync %0, %1;" :: "r"(id), "r"(cnt) : "memory");
}

constexpr int LD   = 68;  // flash Q/K/P smem stride (words)
constexpr int LDV  = 72;  // flash V smem stride
constexpr int LDG_ = 36;  // GEMM smem stride (BK=32 + 4)

// ---------------------------------------------------------------------------
// Pre-round inputs to tf32 (once)
// ---------------------------------------------------------------------------
template <int W>
__global__ void precvt_kernel(const float* __restrict__ src, int n4) {
    int i = blockIdx.x * blockDim.x + threadIdx.x;
    if (i >= n4) return;
    float4 v = ((const float4*)src)[i];
    float* dst = (W == 0) ? g_xt : (W == 1) ? g_wqkvt : g_wprojt;
    ((uint4*)dst)[i] = make_uint4(f2tf(v.x), f2tf(v.y), f2tf(v.z), f2tf(v.w));
}

// ---------------------------------------------------------------------------
// tf32 GEMM, register prefetch + double-buffered smem (ONE sync per chunk).
// C(M x Ncols) = A(M x 768) @ W(Ncols x 768)^T
// 256 threads = 8 warps (4 row-groups x 2 col-groups), warp tile m32 x n64.
// BM=BN=128, BK=32. Dynamic smem: A0 A1 B0 B1 (4 x 4608 words = 73728 B).
// ---------------------------------------------------------------------------
template <int MODE>
__global__ void __launch_bounds__(256, 2) gemm_tf32_kernel(const float* __restrict__ bias,
                                                           float* __restrict__ out,
                                                           int M) {
    extern __shared__ uint32_t gsm[];

    const uint32_t* A  = (MODE == 0) ? (const uint32_t*)g_xt   : (const uint32_t*)g_att;
    const uint32_t* Wm = (MODE == 0) ? (const uint32_t*)g_wqkvt : (const uint32_t*)g_wprojt;

    const int bm = blockIdx.y * 128;
    const int bn = blockIdx.x * 128;
    const int tid = threadIdx.x;
    const int warp = tid >> 5, lane = tid & 31;
    const int wr = warp >> 1, wc = warp & 1;
    const int g = lane >> 2, t = lane & 3;
    const int ar = wr * 32 + g;

    const int frow = tid >> 3;            // 0..31  (+32 per r)
    const int fcol = (tid & 7) << 2;      // 0,4,...,28

    float acc0[8][4], acc1[8][4];
    #pragma unroll
    for (int i = 0; i < 8; i++)
        #pragma unroll
        for (int j = 0; j < 4; j++) { acc0[i][j] = 0.f; acc1[i][j] = 0.f; }

    uint4 pa[4], pb[4];
    auto prefetch = [&](int k0) {
        #pragma unroll
        for (int r = 0; r < 4; r++) {
            int row = frow + 32 * r;
            int arow = min(bm + row, M - 1);   // clamp: finite; epilogue guards
            pa[r] = *(const uint4*)&A[(size_t)arow * DIM_ + k0 + fcol];
            pb[r] = *(const uint4*)&Wm[(size_t)(bn + row) * DIM_ + k0 + fcol];
        }
    };

    prefetch(0);

    for (int kc = 0; kc < 24; kc++) {
        uint32_t* As = gsm + (kc & 1) * 4608;
        uint32_t* Bs = gsm + 9216 + (kc & 1) * 4608;

        // STS chunk kc (other warps may still be computing chunk kc-1 from
        // the other buffer -- this store overlaps their mma)
        #pragma unroll
        for (int r = 0; r < 4; r++) {
            int row = frow + 32 * r;
            *(uint4*)&As[row * LDG_ + fcol] = pa[r];
            *(uint4*)&Bs[row * LDG_ + fcol] = pb[r];
        }
        if (kc + 1 < 24) prefetch((kc + 1) * 32);   // LDGs fly during compute
        __syncthreads();                            // buf[kc&1] visible to all

        #pragma unroll
        for (int ks = 0; ks < 4; ks++) {
            const int kcc = ks * 8;
            uint32_t a0[4], a1[4];
            a0[0] = As[(ar +  0) * LDG_ + kcc + t];
            a0[1] = As[(ar +  8) * LDG_ + kcc + t];
            a0[2] = As[(ar +  0) * LDG_ + kcc + t + 4];
            a0[3] = As[(ar +  8) * LDG_ + kcc + t + 4];
            a1[0] = As[(ar + 16) * LDG_ + kcc + t];
            a1[1] = As[(ar + 24) * LDG_ + kcc + t];
            a1[2] = As[(ar + 16) * LDG_ + kcc + t + 4];
            a1[3] = As[(ar + 24) * LDG_ + kcc + t + 4];
            #pragma unroll
            for (int nt = 0; nt < 8; nt++) {
                uint32_t b[2];
                const int br = wc * 64 + nt * 8 + g;
                b[0] = Bs[br * LDG_ + kcc + t];
                b[1] = Bs[br * LDG_ + kcc + t + 4];
                mma_tf32(acc0[nt], a0, b);
                mma_tf32(acc1[nt], a1, b);
            }
        }
        // no trailing sync: next iter writes the OTHER buffer; the next
        // iter's sync orders reuse of this one.
    }

    const int rows[4] = { bm + ar, bm + ar + 8, bm + ar + 16, bm + ar + 24 };
    #pragma unroll
    for (int nt = 0; nt < 8; nt++) {
        const int c0 = bn + wc * 64 + nt * 8 + 2 * t;
        float vals[4][2] = {
            {acc0[nt][0], acc0[nt][1]}, {acc0[nt][2], acc0[nt][3]},
            {acc1[nt][0], acc1[nt][1]}, {acc1[nt][2], acc1[nt][3]} };
        if (MODE == 0) {
            int which = c0 / DIM_;
            int rem = c0 - which * DIM_;
            int h = rem >> 6, d = rem & 63;
            float* dstf = (which == 0) ? g_Q : (which == 1) ? g_K : g_V;
            #pragma unroll
            for (int rr = 0; rr < 4; rr++) {
                int gm = rows[rr];
                if (gm < M) {
                    int b = gm / N_, n = gm - b * N_;
                    uint2 o = make_uint2(f2tf(vals[rr][0]), f2tf(vals[rr][1]));
                    *(uint2*)((uint32_t*)dstf +
                              (size_t)((b * H_ + h) * N_ + n) * HD_ + d) = o;
                }
            }
        } else {
            float bx = bias[c0], by = bias[c0 + 1];
            #pragma unroll
            for (int rr = 0; rr < 4; rr++) {
                int gm = rows[rr];
                if (gm < M) {
                    float2 o = make_float2(vals[rr][0] + bx, vals[rr][1] + by);
                    *(float2*)&out[(size_t)gm * DIM_ + c0] = o;
                }
            }
        }
    }
}

// ---------------------------------------------------------------------------
// cls scores (unroped, before rope)
// ---------------------------------------------------------------------------
__global__ void __launch_bounds__(256) cls_kernel() {
    int bh = blockIdx.x;
    int warp = threadIdx.x >> 5, lane = threadIdx.x & 31;
    int i = blockIdx.y * 8 + warp;
    if (i >= N_) return;
    const float2* Qi = (const float2*)(g_Q + ((size_t)bh * N_ + i) * HD_);
    const float2* K0 = (const float2*)(g_K + (size_t)bh * N_ * HD_);
    const float2* Q0 = (const float2*)(g_Q + (size_t)bh * N_ * HD_);
    const float2* Ki = (const float2*)(g_K + ((size_t)bh * N_ + i) * HD_);
    float2 a = Qi[lane], b0 = K0[lane], c = Q0[lane], d = Ki[lane];
    float s = a.x * b0.x + a.y * b0.y;
    float r = c.x * d.x + c.y * d.y;
    #pragma unroll
    for (int off = 16; off; off >>= 1) {
        s += __shfl_xor_sync(0xffffffffu, s, off);
        r += __shfl_xor_sync(0xffffffffu, r, off);
    }
    if (lane == 0) {
        g_col0[bh * N_ + i] = s;
        g_row0[bh * N_ + i] = r;
    }
}

// ---------------------------------------------------------------------------
// 2D RoPE in place on Q,K for n >= 1; outputs tf32-rounded
// ---------------------------------------------------------------------------
__global__ void rope_kernel(const int* __restrict__ xpos) {
    int b = blockIdx.x;
    int n = blockIdx.y + 1;
    int h = threadIdx.x >> 5;
    int lane = threadIdx.x & 31;
    int half = lane >> 4;
    int fi = lane & 15;
    float pos = (float)xpos[(b * N_ + n) * 2 + half];
    float inv = powf(100.f, -(float)fi / 16.f);
    float ang = pos * inv;
    float sv, cv;
    sincosf(ang, &sv, &cv);
    size_t base = ((size_t)(b * H_ + h) * N_ + n) * HD_ + half * 32;
    float t1 = g_Q[base + fi], t2 = g_Q[base + fi + 16];
    ((uint32_t*)g_Q)[base + fi]      = f2tf(t1 * cv - t2 * sv);
    ((uint32_t*)g_Q)[base + fi + 16] = f2tf(t2 * cv + t1 * sv);
    t1 = g_K[base + fi]; t2 = g_K[base + fi + 16];
    ((uint32_t*)g_K)[base + fi]      = f2tf(t1 * cv - t2 * sv);
    ((uint32_t*)g_K)[base + fi + 16] = f2tf(t2 * cv + t1 * sv);
}

// ---------------------------------------------------------------------------
// Flash attention, split-K warp groups. 256 threads = 2 groups x 4 warps.
// Group g handles k-tiles g, g+2, ... with private K/V/P buffers and named
// barriers; block-wide merge of (m, l, O) at the end.
// smem (words): Qs[128*LD] | Ks[2][64*LD] | Vs[2][64*LDV] | Ps[2][128*LD]
//               | mbuf[128*73 floats]
// ---------------------------------------------------------------------------
constexpr int FL_QS = 128 * LD;        // 8704
constexpr int FL_KS = 64 * LD;         // 4352 per group
constexpr int FL_VS = 64 * LDV;        // 4608 per group
constexpr int FL_PS = 128 * LD;        // 8704 per group
constexpr int FL_MB_OFF = FL_QS + 2 * FL_KS + 2 * FL_VS + 2 * FL_PS;  // 44032
constexpr int FLASH_SMEM = (FL_MB_OFF + 128 * 73) * 4;                // 213504

__global__ void __launch_bounds__(256) flash_tf32_kernel() {
    extern __shared__ uint32_t sm[];
    uint32_t* Qs = sm;

    const uint32_t* Qg = (const uint32_t*)g_Q;
    const uint32_t* Kg = (const uint32_t*)g_K;
    const uint32_t* Vg = (const uint32_t*)g_V;

    const int bh = blockIdx.x;
    const int qbase = blockIdx.y * 128;
    const int tid = threadIdx.x;
    const int warp = tid >> 5, lane = tid & 31;
    const int group = warp >> 2;          // 0 or 1
    const int gwarp = warp & 3;
    const int gt = tid & 127;
    const int g = lane >> 2, t = lane & 3;
    const int barid = 1 + group;

    uint32_t* Ks = sm + FL_QS + group * FL_KS;
    uint32_t* Vs = sm + FL_QS + 2 * FL_KS + group * FL_VS;
    uint32_t* Ps = sm + FL_QS + 2 * FL_KS + 2 * FL_VS + group * FL_PS;
    float* mbuf = (float*)(sm + FL_MB_OFF);

    // Q fill: all 256 threads
    #pragma unroll
    for (int r = 0; r < 8; r++) {
        int idx = tid + 256 * r;
        int row = idx >> 4;
        int col = (idx & 15) << 2;
        int q = min(qbase + row, N_ - 1);
        *(uint4*)&Qs[row * LD + col] =
            *(const uint4*)&Qg[((size_t)bh * N_ + q) * HD_ + col];
    }
    __syncthreads();

    float oacc0[8][4], oacc1[8][4];
    #pragma unroll
    for (int i = 0; i < 8; i++)
        #pragma unroll
        for (int j = 0; j < 4; j++) { oacc0[i][j] = 0.f; oacc1[i][j] = 0.f; }
    float m[4] = {-1e30f, -1e30f, -1e30f, -1e30f};
    float l[4] = {0.f, 0.f, 0.f, 0.f};

    const int pr0 = gwarp * 32 + g;
    const int rq[4] = { qbase + pr0, qbase + pr0 + 8,
                        qbase + pr0 + 16, qbase + pr0 + 24 };
    float colv[4];
    #pragma unroll
    for (int rr = 0; rr < 4; rr++) colv[rr] = g_col0[bh * N_ + min(rq[rr], N_ - 1)];
    const bool qzero = (rq[0] == 0);

    for (int it = group; it < 17; it += 2) {
        const int kt = it * 64;
        bar_named(barid, 128);               // prior PV reads of Ks/Vs done
        #pragma unroll
        for (int r = 0; r < 8; r++) {
            int idx = gt + 128 * r;
            int row = idx >> 4;
            int col = (idx & 15) << 2;
            int k = kt + row;
            uint4 kv = make_uint4(0u, 0u, 0u, 0u);
            uint4 vv = make_uint4(0u, 0u, 0u, 0u);
            if (k < N_) {
                kv = *(const uint4*)&Kg[((size_t)bh * N_ + k) * HD_ + col];
                vv = *(const uint4*)&Vg[((size_t)bh * N_ + k) * HD_ + col];
            }
            *(uint4*)&Ks[row * LD + col] = kv;
            *(uint4*)&Vs[row * LDV + col] = vv;
        }
        bar_named(barid, 128);

        float sacc0[8][4], sacc1[8][4];
        #pragma unroll
        for (int i = 0; i < 8; i++)
            #pragma unroll
            for (int j = 0; j < 4; j++) { sacc0[i][j] = 0.f; sacc1[i][j] = 0.f; }

        #pragma unroll
        for (int ks = 0; ks < 8; ks++) {
            const int kc = ks * 8;
            uint32_t a0[4], a1[4];
            a0[0] = Qs[(pr0 +  0) * LD + kc + t];
            a0[1] = Qs[(pr0 +  8) * LD + kc + t];
            a0[2] = Qs[(pr0 +  0) * LD + kc + t + 4];
            a0[3] = Qs[(pr0 +  8) * LD + kc + t + 4];
            a1[0] = Qs[(pr0 + 16) * LD + kc + t];
            a1[1] = Qs[(pr0 + 24) * LD + kc + t];
            a1[2] = Qs[(pr0 + 16) * LD + kc + t + 4];
            a1[3] = Qs[(pr0 + 24) * LD + kc + t + 4];
            #pragma unroll
            for (int nt = 0; nt < 8; nt++) {
                uint32_t b[2];
                const int br = nt * 8 + g;
                b[0] = Ks[br * LD + kc + t];
                b[1] = Ks[br * LD + kc + t + 4];
                mma_tf32(sacc0[nt], a0, b);
                mma_tf32(sacc1[nt], a1, b);
            }
        }

        #pragma unroll
        for (int nt = 0; nt < 8; nt++) {
            #pragma unroll
            for (int c = 0; c < 4; c++) {
                int kcol = kt + nt * 8 + 2 * t + (c & 1);
                float s0 = sacc0[nt][c];
                float s1 = sacc1[nt][c];
                if (kcol >= N_) {
                    s0 = -1e30f; s1 = -1e30f;
                } else {
                    if (kcol == 0) {
                        s0 = (c < 2) ? colv[0] : colv[1];
                        s1 = (c < 2) ? colv[2] : colv[3];
                    }
                    if (qzero && c < 2) s0 = g_row0[bh * N_ + kcol];
                    s0 *= SCALE; s1 *= SCALE;
                }
                sacc0[nt][c] = s0;
                sacc1[nt][c] = s1;
            }
        }

        #pragma unroll
        for (int hh = 0; hh < 4; hh++) {
            float (*sa)[4] = (hh < 2) ? sacc0 : sacc1;
            float (*oa)[4] = (hh < 2) ? oacc0 : oacc1;
            const int co = (hh & 1) * 2;
            float mx = -1e30f;
            #pragma unroll
            for (int nt = 0; nt < 8; nt++)
                mx = fmaxf(mx, fmaxf(sa[nt][co], sa[nt][co + 1]));
            mx = fmaxf(mx, __shfl_xor_sync(0xffffffffu, mx, 1));
            mx = fmaxf(mx, __shfl_xor_sync(0xffffffffu, mx, 2));
            float mn = fmaxf(m[hh], mx);
            float corr = __expf(m[hh] - mn);
            m[hh] = mn;
            float ls = 0.f;
            #pragma unroll
            for (int nt = 0; nt < 8; nt++) {
                float p0 = __expf(sa[nt][co] - mn);
                float p1 = __expf(sa[nt][co + 1] - mn);
                ls += p0 + p1;
                sa[nt][co] = p0;
                sa[nt][co + 1] = p1;
            }
            l[hh] = l[hh] * corr + ls;
            #pragma unroll
            for (int nt = 0; nt < 8; nt++) {
                oa[nt][co] *= corr;
                oa[nt][co + 1] *= corr;
            }
        }

        #pragma unroll
        for (int nt = 0; nt < 8; nt++) {
            int kc = nt * 8 + 2 * t;
            *(uint2*)&Ps[(pr0 +  0) * LD + kc] = make_uint2(f2tf(sacc0[nt][0]), f2tf(sacc0[nt][1]));
            *(uint2*)&Ps[(pr0 +  8) * LD + kc] = make_uint2(f2tf(sacc0[nt][2]), f2tf(sacc0[nt][3]));
            *(uint2*)&Ps[(pr0 + 16) * LD + kc] = make_uint2(f2tf(sacc1[nt][0]), f2tf(sacc1[nt][1]));
            *(uint2*)&Ps[(pr0 + 24) * LD + kc] = make_uint2(f2tf(sacc1[nt][2]), f2tf(sacc1[nt][3]));
        }
        __syncwarp();

        #pragma unroll
        for (int ks = 0; ks < 8; ks++) {
            const int kc = ks * 8;
            uint32_t a0[4], a1[4];
            a0[0] = Ps[(pr0 +  0) * LD + kc + t];
            a0[1] = Ps[(pr0 +  8) * LD + kc + t];
            a0[2] = Ps[(pr0 +  0) * LD + kc + t + 4];
            a0[3] = Ps[(pr0 +  8) * LD + kc + t + 4];
            a1[0] = Ps[(pr0 + 16) * LD + kc + t];
            a1[1] = Ps[(pr0 + 24) * LD + kc + t];
            a1[2] = Ps[(pr0 + 16) * LD + kc + t + 4];
            a1[3] = Ps[(pr0 + 24) * LD + kc + t + 4];
            #pragma unroll
            for (int nt = 0; nt < 8; nt++) {
                uint32_t b[2];
                b[0] = Vs[(kc + t) * LDV + nt * 8 + g];
                b[1] = Vs[(kc + t + 4) * LDV + nt * 8 + g];
                mma_tf32(oacc0[nt], a0, b);
                mma_tf32(oacc1[nt], a1, b);
            }
        }
    }

    // reduce l within each 4-lane row group (per warp group)
    #pragma unroll
    for (int hh = 0; hh < 4; hh++) {
        l[hh] += __shfl_xor_sync(0xffffffffu, l[hh], 1);
        l[hh] += __shfl_xor_sync(0xffffffffu, l[hh], 2);
    }

    __syncthreads();   // both groups done (incl. group B's Ps reads)
    if (group == 1) {
        float* mb = mbuf + gt * 73;
        #pragma unroll
        for (int hh = 0; hh < 4; hh++) { mb[hh] = m[hh]; mb[4 + hh] = l[hh]; }
        #pragma unroll
        for (int nt = 0; nt < 8; nt++)
            #pragma unroll
            for (int c = 0; c < 4; c++) {
                mb[8  + nt * 4 + c] = oacc0[nt][c];
                mb[40 + nt * 4 + c] = oacc1[nt][c];
            }
    }
    __syncthreads();
    if (group == 0) {
        const float* mb = mbuf + gt * 73;
        float sA[4], sB[4], linv[4];
        #pragma unroll
        for (int hh = 0; hh < 4; hh++) {
            float mB = mb[hh], lB = mb[4 + hh];
            float mm = fmaxf(m[hh], mB);
            sA[hh] = __expf(m[hh] - mm);
            sB[hh] = __expf(mB - mm);
            linv[hh] = 1.f / (l[hh] * sA[hh] + lB * sB[hh]);
        }
        const int b = bh / H_, h = bh - b * H_;
        uint32_t* att = (uint32_t*)g_att;
        #pragma unroll
        for (int nt = 0; nt < 8; nt++) {
            int d = nt * 8 + 2 * t;
            float vals[4][2];
            #pragma unroll
            for (int c = 0; c < 2; c++) {
                vals[0][c] = (oacc0[nt][c]     * sA[0] + mb[8  + nt*4 + c]     * sB[0]) * linv[0];
                vals[1][c] = (oacc0[nt][c + 2] * sA[1] + mb[8  + nt*4 + c + 2] * sB[1]) * linv[1];
                vals[2][c] = (oacc1[nt][c]     * sA[2] + mb[40 + nt*4 + c]     * sB[2]) * linv[2];
                vals[3][c] = (oacc1[nt][c + 2] * sA[3] + mb[40 + nt*4 + c + 2] * sB[3]) * linv[3];
            }
            #pragma unroll
            for (int rr = 0; rr < 4; rr++) {
                if (rq[rr] < N_) {
                    uint2 o = make_uint2(f2tf(vals[rr][0]), f2tf(vals[rr][1]));
                    *(uint2*)&att[((size_t)(b * N_ + rq[rr])) * DIM_ + h * HD_ + d] = o;
                }
            }
        }
    }
}

// ---------------------------------------------------------------------------
constexpr int GEMM_SMEM = 4 * 4608 * 4;   // 73728

extern "C" void kernel_launch(void* const* d_in, const int* in_sizes, int n_in,
                              void* d_out, int out_size) {
    int ix = -1, ixpos = -1, iwqkv = -1, iwproj = -1, ibproj = -1;
    for (int k = 0; k < n_in; k++) {
        switch (in_sizes[k]) {
            case NTOK * DIM_:  ix = k; break;
            case NTOK * 2:     ixpos = k; break;
            case C3 * DIM_:    iwqkv = k; break;
            case DIM_ * DIM_:  iwproj = k; break;
            case DIM_:         ibproj = k; break;
            default: break;
        }
    }
    const float* x      = (const float*)d_in[ix];
    const int*   xpos   = (const int*)d_in[ixpos];
    const float* w_qkv  = (const float*)d_in[iwqkv];
    const float* w_proj = (const float*)d_in[iwproj];
    const float* b_proj = (const float*)d_in[ibproj];
    float* out = (float*)d_out;

    cudaFuncSetAttribute(gemm_tf32_kernel<0>, cudaFuncAttributeMaxDynamicSharedMemorySize, GEMM_SMEM);
    cudaFuncSetAttribute(gemm_tf32_kernel<1>, cudaFuncAttributeMaxDynamicSharedMemorySize, GEMM_SMEM);
    cudaFuncSetAttribute(flash_tf32_kernel,   cudaFuncAttributeMaxDynamicSharedMemorySize, FLASH_SMEM);

    const int mtiles = (NTOK + 127) / 128;   // 65

    precvt_kernel<0><<<(NTOK * DIM_ / 4 + 255) / 256, 256>>>(x, NTOK * DIM_ / 4);
    precvt_kernel<1><<<(C3 * DIM_ / 4 + 255) / 256, 256>>>(w_qkv, C3 * DIM_ / 4);
    precvt_kernel<2><<<(DIM_ * DIM_ / 4 + 255) / 256, 256>>>(w_proj, DIM_ * DIM_ / 4);

    gemm_tf32_kernel<0><<<dim3(C3 / 128, mtiles), 256, GEMM_SMEM>>>(nullptr, nullptr, NTOK);
    cls_kernel<<<dim3(BH, (N_ + 7) / 8), 256>>>();
    rope_kernel<<<dim3(B_, N_ - 1), H_ * 32>>>(xpos);
    flash_tf32_kernel<<<dim3(BH, (N_ + 127) / 128), 256, FLASH_SMEM>>>();
    gemm_tf32_kernel<1><<<dim3(DIM_ / 128, mtiles), 256, GEMM_SMEM>>>(b_proj, out, NTOK);
}

// round 11
// speedup vs baseline: 1.1447x; 1.1447x over previous
#include <cuda_runtime.h>
#include <math.h>
#include <stdint.h>

// Problem constants
constexpr int B_   = 8;
constexpr int N_   = 1025;
constexpr int H_   = 12;
constexpr int HD_  = 64;
constexpr int DIM_ = 768;
constexpr int NTOK = B_ * N_;     // 8200
constexpr int C3   = 3 * DIM_;    // 2304
constexpr int BH   = B_ * H_;     // 96
constexpr float SCALE = 0.125f;

// Scratch (tf32-rounded-in-fp32 unless noted)
__device__ float g_Q[(size_t)BH * N_ * HD_];
__device__ float g_K[(size_t)BH * N_ * HD_];
__device__ float g_V[(size_t)BH * N_ * HD_];
__device__ float g_col0[BH * N_];              // fp32
__device__ float g_row0[BH * N_];              // fp32
__device__ float g_att[(size_t)NTOK * DIM_];
__device__ float g_xt[(size_t)NTOK * DIM_];
__device__ float g_wqkvt[C3 * DIM_];
__device__ float g_wprojt[DIM_ * DIM_];

// ---------------------------------------------------------------------------
__device__ __forceinline__ uint32_t f2tf(float f) {
    uint32_t u;
    asm("cvt.rna.tf32.f32 %0, %1;" : "=r"(u) : "f"(f));
    return u;
}

__device__ __forceinline__ void mma_tf32(float* d, const uint32_t* a, const uint32_t* b) {
    asm volatile(
        "mma.sync.aligned.m16n8k8.row.col.f32.tf32.tf32.f32 "
        "{%0,%1,%2,%3}, {%4,%5,%6,%7}, {%8,%9}, {%0,%1,%2,%3};\n"
        : "+f"(d[0]), "+f"(d[1]), "+f"(d[2]), "+f"(d[3])
        : "r"(a[0]), "r"(a[1]), "r"(a[2]), "r"(a[3]), "r"(b[0]), "r"(b[1]));
}

constexpr int LD   = 68;  // flash Q/K/P smem stride (words)
constexpr int LDV  = 72;  // flash V smem stride
constexpr int LDG_ = 36;  // GEMM smem stride (BK=32 + 4)

// ---------------------------------------------------------------------------
// Pre-round inputs to tf32 (once)
// ---------------------------------------------------------------------------
template <int W>
__global__ void precvt_kernel(const float* __restrict__ src, int n4) {
    int i = blockIdx.x * blockDim.x + threadIdx.x;
    if (i >= n4) return;
    float4 v = ((const float4*)src)[i];
    float* dst = (W == 0) ? g_xt : (W == 1) ? g_wqkvt : g_wprojt;
    ((uint4*)dst)[i] = make_uint4(f2tf(v.x), f2tf(v.y), f2tf(v.z), f2tf(v.w));
}

// ---------------------------------------------------------------------------
// tf32 GEMM (round-10 proven version, 189 us): register prefetch +
// double-buffered smem, ONE sync per chunk.
// 256 threads = 8 warps (4 row-groups x 2 col-groups), warp tile m32 x n64.
// BM=BN=128, BK=32. Dynamic smem: A0 A1 B0 B1 (4 x 4608 words = 73728 B).
// ---------------------------------------------------------------------------
template <int MODE>
__global__ void __launch_bounds__(256, 2) gemm_tf32_kernel(const float* __restrict__ bias,
                                                           float* __restrict__ out,
                                                           int M) {
    extern __shared__ uint32_t gsm[];

    const uint32_t* A  = (MODE == 0) ? (const uint32_t*)g_xt   : (const uint32_t*)g_att;
    const uint32_t* Wm = (MODE == 0) ? (const uint32_t*)g_wqkvt : (const uint32_t*)g_wprojt;

    const int bm = blockIdx.y * 128;
    const int bn = blockIdx.x * 128;
    const int tid = threadIdx.x;
    const int warp = tid >> 5, lane = tid & 31;
    const int wr = warp >> 1, wc = warp & 1;
    const int g = lane >> 2, t = lane & 3;
    const int ar = wr * 32 + g;

    const int frow = tid >> 3;            // 0..31  (+32 per r)
    const int fcol = (tid & 7) << 2;      // 0,4,...,28

    float acc0[8][4], acc1[8][4];
    #pragma unroll
    for (int i = 0; i < 8; i++)
        #pragma unroll
        for (int j = 0; j < 4; j++) { acc0[i][j] = 0.f; acc1[i][j] = 0.f; }

    uint4 pa[4], pb[4];
    auto prefetch = [&](int k0) {
        #pragma unroll
        for (int r = 0; r < 4; r++) {
            int row = frow + 32 * r;
            int arow = min(bm + row, M - 1);   // clamp: finite; epilogue guards
            pa[r] = *(const uint4*)&A[(size_t)arow * DIM_ + k0 + fcol];
            pb[r] = *(const uint4*)&Wm[(size_t)(bn + row) * DIM_ + k0 + fcol];
        }
    };

    prefetch(0);

    for (int kc = 0; kc < 24; kc++) {
        uint32_t* As = gsm + (kc & 1) * 4608;
        uint32_t* Bs = gsm + 9216 + (kc & 1) * 4608;

        #pragma unroll
        for (int r = 0; r < 4; r++) {
            int row = frow + 32 * r;
            *(uint4*)&As[row * LDG_ + fcol] = pa[r];
            *(uint4*)&Bs[row * LDG_ + fcol] = pb[r];
        }
        if (kc + 1 < 24) prefetch((kc + 1) * 32);
        __syncthreads();

        #pragma unroll
        for (int ks = 0; ks < 4; ks++) {
            const int kcc = ks * 8;
            uint32_t a0[4], a1[4];
            a0[0] = As[(ar +  0) * LDG_ + kcc + t];
            a0[1] = As[(ar +  8) * LDG_ + kcc + t];
            a0[2] = As[(ar +  0) * LDG_ + kcc + t + 4];
            a0[3] = As[(ar +  8) * LDG_ + kcc + t + 4];
            a1[0] = As[(ar + 16) * LDG_ + kcc + t];
            a1[1] = As[(ar + 24) * LDG_ + kcc + t];
            a1[2] = As[(ar + 16) * LDG_ + kcc + t + 4];
            a1[3] = As[(ar + 24) * LDG_ + kcc + t + 4];
            #pragma unroll
            for (int nt = 0; nt < 8; nt++) {
                uint32_t b[2];
                const int br = wc * 64 + nt * 8 + g;
                b[0] = Bs[br * LDG_ + kcc + t];
                b[1] = Bs[br * LDG_ + kcc + t + 4];
                mma_tf32(acc0[nt], a0, b);
                mma_tf32(acc1[nt], a1, b);
            }
        }
        // no trailing sync: next iter writes the OTHER buffer
    }

    const int rows[4] = { bm + ar, bm + ar + 8, bm + ar + 16, bm + ar + 24 };
    #pragma unroll
    for (int nt = 0; nt < 8; nt++) {
        const int c0 = bn + wc * 64 + nt * 8 + 2 * t;
        float vals[4][2] = {
            {acc0[nt][0], acc0[nt][1]}, {acc0[nt][2], acc0[nt][3]},
            {acc1[nt][0], acc1[nt][1]}, {acc1[nt][2], acc1[nt][3]} };
        if (MODE == 0) {
            int which = c0 / DIM_;
            int rem = c0 - which * DIM_;
            int h = rem >> 6, d = rem & 63;
            float* dstf = (which == 0) ? g_Q : (which == 1) ? g_K : g_V;
            #pragma unroll
            for (int rr = 0; rr < 4; rr++) {
                int gm = rows[rr];
                if (gm < M) {
                    int b = gm / N_, n = gm - b * N_;
                    uint2 o = make_uint2(f2tf(vals[rr][0]), f2tf(vals[rr][1]));
                    *(uint2*)((uint32_t*)dstf +
                              (size_t)((b * H_ + h) * N_ + n) * HD_ + d) = o;
                }
            }
        } else {
            float bx = bias[c0], by = bias[c0 + 1];
            #pragma unroll
            for (int rr = 0; rr < 4; rr++) {
                int gm = rows[rr];
                if (gm < M) {
                    float2 o = make_float2(vals[rr][0] + bx, vals[rr][1] + by);
                    *(float2*)&out[(size_t)gm * DIM_ + c0] = o;
                }
            }
        }
    }
}

// ---------------------------------------------------------------------------
// cls scores (unroped, before rope)
// ---------------------------------------------------------------------------
__global__ void __launch_bounds__(256) cls_kernel() {
    int bh = blockIdx.x;
    int warp = threadIdx.x >> 5, lane = threadIdx.x & 31;
    int i = blockIdx.y * 8 + warp;
    if (i >= N_) return;
    const float2* Qi = (const float2*)(g_Q + ((size_t)bh * N_ + i) * HD_);
    const float2* K0 = (const float2*)(g_K + (size_t)bh * N_ * HD_);
    const float2* Q0 = (const float2*)(g_Q + (size_t)bh * N_ * HD_);
    const float2* Ki = (const float2*)(g_K + ((size_t)bh * N_ + i) * HD_);
    float2 a = Qi[lane], b0 = K0[lane], c = Q0[lane], d = Ki[lane];
    float s = a.x * b0.x + a.y * b0.y;
    float r = c.x * d.x + c.y * d.y;
    #pragma unroll
    for (int off = 16; off; off >>= 1) {
        s += __shfl_xor_sync(0xffffffffu, s, off);
        r += __shfl_xor_sync(0xffffffffu, r, off);
    }
    if (lane == 0) {
        g_col0[bh * N_ + i] = s;
        g_row0[bh * N_ + i] = r;
    }
}

// ---------------------------------------------------------------------------
// 2D RoPE in place on Q,K for n >= 1; outputs tf32-rounded
// ---------------------------------------------------------------------------
__global__ void rope_kernel(const int* __restrict__ xpos) {
    int b = blockIdx.x;
    int n = blockIdx.y + 1;
    int h = threadIdx.x >> 5;
    int lane = threadIdx.x & 31;
    int half = lane >> 4;
    int fi = lane & 15;
    float pos = (float)xpos[(b * N_ + n) * 2 + half];
    float inv = powf(100.f, -(float)fi / 16.f);
    float ang = pos * inv;
    float sv, cv;
    sincosf(ang, &sv, &cv);
    size_t base = ((size_t)(b * H_ + h) * N_ + n) * HD_ + half * 32;
    float t1 = g_Q[base + fi], t2 = g_Q[base + fi + 16];
    ((uint32_t*)g_Q)[base + fi]      = f2tf(t1 * cv - t2 * sv);
    ((uint32_t*)g_Q)[base + fi + 16] = f2tf(t2 * cv + t1 * sv);
    t1 = g_K[base + fi]; t2 = g_K[base + fi + 16];
    ((uint32_t*)g_K)[base + fi]      = f2tf(t1 * cv - t2 * sv);
    ((uint32_t*)g_K)[base + fi + 16] = f2tf(t2 * cv + t1 * sv);
}

// ---------------------------------------------------------------------------
// Flash attention (round-7 structure) with tile-specialized overrides:
// masking only on the last tile, col0 override only on tile 0 (4 scalar
// writes), row0 override only for the qzero threads. Values identical to
// round 7 -- only dead per-element ALU removed.
// ---------------------------------------------------------------------------
__global__ void __launch_bounds__(128) flash_tf32_kernel() {
    extern __shared__ uint32_t sm[];
    uint32_t* Qs = sm;                    // [128][LD]
    uint32_t* Ks = Qs + 128 * LD;         // [64][LD]
    uint32_t* Vs = Ks + 64 * LD;          // [64][LDV]
    uint32_t* Ps = Vs + 64 * LDV;         // [128][LD]

    const uint32_t* Qg = (const uint32_t*)g_Q;
    const uint32_t* Kg = (const uint32_t*)g_K;
    const uint32_t* Vg = (const uint32_t*)g_V;

    const int bh = blockIdx.x;
    const int qbase = blockIdx.y * 128;
    const int tid = threadIdx.x;
    const int warp = tid >> 5, lane = tid & 31;
    const int g = lane >> 2, t = lane & 3;

    #pragma unroll
    for (int r = 0; r < 16; r++) {
        int idx = tid + 128 * r;
        int row = idx >> 4;
        int col = (idx & 15) << 2;
        int q = min(qbase + row, N_ - 1);
        *(uint4*)&Qs[row * LD + col] =
            *(const uint4*)&Qg[((size_t)bh * N_ + q) * HD_ + col];
    }

    float oacc0[8][4], oacc1[8][4];
    #pragma unroll
    for (int i = 0; i < 8; i++)
        #pragma unroll
        for (int j = 0; j < 4; j++) { oacc0[i][j] = 0.f; oacc1[i][j] = 0.f; }
    float m[4] = {-1e30f, -1e30f, -1e30f, -1e30f};
    float l[4] = {0.f, 0.f, 0.f, 0.f};

    const int pr0 = warp * 32 + g;
    const int rq[4] = { qbase + pr0, qbase + pr0 + 8,
                        qbase + pr0 + 16, qbase + pr0 + 24 };
    float colv[4];
    #pragma unroll
    for (int rr = 0; rr < 4; rr++) colv[rr] = g_col0[bh * N_ + min(rq[rr], N_ - 1)];
    const bool qzero = (rq[0] == 0);
    const float* rowp = g_row0 + bh * N_;

    for (int kt = 0; kt < 1088; kt += 64) {
        __syncthreads();
        #pragma unroll
        for (int r = 0; r < 8; r++) {
            int idx = tid + 128 * r;
            int row = idx >> 4;
            int col = (idx & 15) << 2;
            int k = kt + row;
            uint4 kv = make_uint4(0u, 0u, 0u, 0u);
            uint4 vv = make_uint4(0u, 0u, 0u, 0u);
            if (k < N_) {
                kv = *(const uint4*)&Kg[((size_t)bh * N_ + k) * HD_ + col];
                vv = *(const uint4*)&Vg[((size_t)bh * N_ + k) * HD_ + col];
            }
            *(uint4*)&Ks[row * LD + col] = kv;
            *(uint4*)&Vs[row * LDV + col] = vv;
        }
        __syncthreads();

        float sacc0[8][4], sacc1[8][4];
        #pragma unroll
        for (int i = 0; i < 8; i++)
            #pragma unroll
            for (int j = 0; j < 4; j++) { sacc0[i][j] = 0.f; sacc1[i][j] = 0.f; }

        #pragma unroll
        for (int ks = 0; ks < 8; ks++) {
            const int kc = ks * 8;
            uint32_t a0[4], a1[4];
            a0[0] = Qs[(pr0 +  0) * LD + kc + t];
            a0[1] = Qs[(pr0 +  8) * LD + kc + t];
            a0[2] = Qs[(pr0 +  0) * LD + kc + t + 4];
            a0[3] = Qs[(pr0 +  8) * LD + kc + t + 4];
            a1[0] = Qs[(pr0 + 16) * LD + kc + t];
            a1[1] = Qs[(pr0 + 24) * LD + kc + t];
            a1[2] = Qs[(pr0 + 16) * LD + kc + t + 4];
            a1[3] = Qs[(pr0 + 24) * LD + kc + t + 4];
            #pragma unroll
            for (int nt = 0; nt < 8; nt++) {
                uint32_t b[2];
                const int br = nt * 8 + g;
                b[0] = Ks[br * LD + kc + t];
                b[1] = Ks[br * LD + kc + t + 4];
                mma_tf32(sacc0[nt], a0, b);
                mma_tf32(sacc1[nt], a1, b);
            }
        }

        // ---- tile-specialized overrides (same values/precedence as before) --
        if (kt == 1024) {                        // last tile: mask kcol >= N
            #pragma unroll
            for (int nt = 0; nt < 8; nt++)
                #pragma unroll
                for (int c = 0; c < 4; c++) {
                    int kcol = kt + nt * 8 + 2 * t + (c & 1);
                    if (kcol >= N_) { sacc0[nt][c] = -1e30f; sacc1[nt][c] = -1e30f; }
                }
        }
        if (kt == 0 && t == 0) {                 // kcol==0 column override
            sacc0[0][0] = colv[0]; sacc0[0][2] = colv[1];
            sacc1[0][0] = colv[2]; sacc1[0][2] = colv[3];
        }
        if (qzero) {                             // q-row 0 override (c0,c1)
            #pragma unroll
            for (int nt = 0; nt < 8; nt++)
                #pragma unroll
                for (int c = 0; c < 2; c++) {
                    int kcol = kt + nt * 8 + 2 * t + c;
                    if (kcol < N_) sacc0[nt][c] = rowp[kcol];
                }
        }
        #pragma unroll
        for (int nt = 0; nt < 8; nt++)
            #pragma unroll
            for (int c = 0; c < 4; c++) { sacc0[nt][c] *= SCALE; sacc1[nt][c] *= SCALE; }
        // ---------------------------------------------------------------------

        #pragma unroll
        for (int hh = 0; hh < 4; hh++) {
            float (*sa)[4] = (hh < 2) ? sacc0 : sacc1;
            float (*oa)[4] = (hh < 2) ? oacc0 : oacc1;
            const int co = (hh & 1) * 2;
            float mx = -1e30f;
            #pragma unroll
            for (int nt = 0; nt < 8; nt++)
                mx = fmaxf(mx, fmaxf(sa[nt][co], sa[nt][co + 1]));
            mx = fmaxf(mx, __shfl_xor_sync(0xffffffffu, mx, 1));
            mx = fmaxf(mx, __shfl_xor_sync(0xffffffffu, mx, 2));
            float mn = fmaxf(m[hh], mx);
            float corr = __expf(m[hh] - mn);
            m[hh] = mn;
            float ls = 0.f;
            #pragma unroll
            for (int nt = 0; nt < 8; nt++) {
                float p0 = __expf(sa[nt][co] - mn);
                float p1 = __expf(sa[nt][co + 1] - mn);
                ls += p0 + p1;
                sa[nt][co] = p0;
                sa[nt][co + 1] = p1;
            }
            l[hh] = l[hh] * corr + ls;
            #pragma unroll
            for (int nt = 0; nt < 8; nt++) {
                oa[nt][co] *= corr;
                oa[nt][co + 1] *= corr;
            }
        }

        #pragma unroll
        for (int nt = 0; nt < 8; nt++) {
            int kc = nt * 8 + 2 * t;
            *(uint2*)&Ps[(pr0 +  0) * LD + kc] = make_uint2(f2tf(sacc0[nt][0]), f2tf(sacc0[nt][1]));
            *(uint2*)&Ps[(pr0 +  8) * LD + kc] = make_uint2(f2tf(sacc0[nt][2]), f2tf(sacc0[nt][3]));
            *(uint2*)&Ps[(pr0 + 16) * LD + kc] = make_uint2(f2tf(sacc1[nt][0]), f2tf(sacc1[nt][1]));
            *(uint2*)&Ps[(pr0 + 24) * LD + kc] = make_uint2(f2tf(sacc1[nt][2]), f2tf(sacc1[nt][3]));
        }
        __syncwarp();

        #pragma unroll
        for (int ks = 0; ks < 8; ks++) {
            const int kc = ks * 8;
            uint32_t a0[4], a1[4];
            a0[0] = Ps[(pr0 +  0) * LD + kc + t];
            a0[1] = Ps[(pr0 +  8) * LD + kc + t];
            a0[2] = Ps[(pr0 +  0) * LD + kc + t + 4];
            a0[3] = Ps[(pr0 +  8) * LD + kc + t + 4];
            a1[0] = Ps[(pr0 + 16) * LD + kc + t];
            a1[1] = Ps[(pr0 + 24) * LD + kc + t];
            a1[2] = Ps[(pr0 + 16) * LD + kc + t + 4];
            a1[3] = Ps[(pr0 + 24) * LD + kc + t + 4];
            #pragma unroll
            for (int nt = 0; nt < 8; nt++) {
                uint32_t b[2];
                b[0] = Vs[(kc + t) * LDV + nt * 8 + g];
                b[1] = Vs[(kc + t + 4) * LDV + nt * 8 + g];
                mma_tf32(oacc0[nt], a0, b);
                mma_tf32(oacc1[nt], a1, b);
            }
        }
    }

    #pragma unroll
    for (int hh = 0; hh < 4; hh++) {
        l[hh] += __shfl_xor_sync(0xffffffffu, l[hh], 1);
        l[hh] += __shfl_xor_sync(0xffffffffu, l[hh], 2);
        l[hh] = 1.f / l[hh];
    }
    const int b = bh / H_, h = bh - b * H_;
    uint32_t* att = (uint32_t*)g_att;
    #pragma unroll
    for (int nt = 0; nt < 8; nt++) {
        int d = nt * 8 + 2 * t;
        float vals[4][2] = {
            {oacc0[nt][0], oacc0[nt][1]}, {oacc0[nt][2], oacc0[nt][3]},
            {oacc1[nt][0], oacc1[nt][1]}, {oacc1[nt][2], oacc1[nt][3]} };
        #pragma unroll
        for (int rr = 0; rr < 4; rr++) {
            if (rq[rr] < N_) {
                uint2 o = make_uint2(f2tf(vals[rr][0] * l[rr]), f2tf(vals[rr][1] * l[rr]));
                *(uint2*)&att[((size_t)(b * N_ + rq[rr])) * DIM_ + h * HD_ + d] = o;
            }
        }
    }
}

// ---------------------------------------------------------------------------
constexpr int GEMM_SMEM  = 4 * 4608 * 4;                                    // 73728
constexpr int FLASH_SMEM = (128 * LD + 64 * LD + 64 * LDV + 128 * LD) * 4;  // 105472

extern "C" void kernel_launch(void* const* d_in, const int* in_sizes, int n_in,
                              void* d_out, int out_size) {
    int ix = -1, ixpos = -1, iwqkv = -1, iwproj = -1, ibproj = -1;
    for (int k = 0; k < n_in; k++) {
        switch (in_sizes[k]) {
            case NTOK * DIM_:  ix = k; break;
            case NTOK * 2:     ixpos = k; break;
            case C3 * DIM_:    iwqkv = k; break;
            case DIM_ * DIM_:  iwproj = k; break;
            case DIM_:         ibproj = k; break;
            default: break;
        }
    }
    const float* x      = (const float*)d_in[ix];
    const int*   xpos   = (const int*)d_in[ixpos];
    const float* w_qkv  = (const float*)d_in[iwqkv];
    const float* w_proj = (const float*)d_in[iwproj];
    const float* b_proj = (const float*)d_in[ibproj];
    float* out = (float*)d_out;

    cudaFuncSetAttribute(gemm_tf32_kernel<0>, cudaFuncAttributeMaxDynamicSharedMemorySize, GEMM_SMEM);
    cudaFuncSetAttribute(gemm_tf32_kernel<1>, cudaFuncAttributeMaxDynamicSharedMemorySize, GEMM_SMEM);
    cudaFuncSetAttribute(flash_tf32_kernel,   cudaFuncAttributeMaxDynamicSharedMemorySize, FLASH_SMEM);

    const int mtiles = (NTOK + 127) / 128;   // 65

    precvt_kernel<0><<<(NTOK * DIM_ / 4 + 255) / 256, 256>>>(x, NTOK * DIM_ / 4);
    precvt_kernel<1><<<(C3 * DIM_ / 4 + 255) / 256, 256>>>(w_qkv, C3 * DIM_ / 4);
    precvt_kernel<2><<<(DIM_ * DIM_ / 4 + 255) / 256, 256>>>(w_proj, DIM_ * DIM_ / 4);

    gemm_tf32_kernel<0><<<dim3(C3 / 128, mtiles), 256, GEMM_SMEM>>>(nullptr, nullptr, NTOK);
    cls_kernel<<<dim3(BH, (N_ + 7) / 8), 256>>>();
    rope_kernel<<<dim3(B_, N_ - 1), H_ * 32>>>(xpos);
    flash_tf32_kernel<<<dim3(BH, (N_ + 127) / 128), 128, FLASH_SMEM>>>();
    gemm_tf32_kernel<1><<<dim3(DIM_ / 128, mtiles), 256, GEMM_SMEM>>>(b_proj, out, NTOK);
}